// round 1
// baseline (speedup 1.0000x reference)
#include <cuda_runtime.h>

#define LRELU_ALPHA 0.2f

constexpr int N    = 8192;
constexpr int KIN  = 512;
constexpr int OUTD = 256;
constexpr int W257 = OUTD + 1;   // 256 feature columns + 1 scalar (weight-sum) column
constexpr int NCH  = 256;        // scan chunks
constexpr int CHL  = N / NCH;    // 32 rows per chunk

// ---------------- scratch (device globals; no allocation) ----------------
__device__ float g_h[N * OUTD];             // h = x @ W^T
__device__ float g_s2[N];                   // s2 = h @ a2
__device__ float g_key[N];                  // s1 (then sorted ascending)
__device__ int   g_idx[N];                  // sort permutation
__device__ float g_cs1[NCH * W257];         // per-chunk sums, exp branch
__device__ float g_cs2[NCH * W257];         // per-chunk sums, alpha branch
__device__ float g_co1[NCH * W257];         // suffix offsets (exp branch)
__device__ float g_co2[NCH * W257];         // prefix offsets (alpha branch)
__device__ float g_SE[(N + 1) * W257];      // suffix sums of exp(s1-m1)*h  (incl. from p)
__device__ float g_P2[(N + 1) * W257];      // prefix sums of exp(a*(s1-m1))*h (excl.)

// ---------------- GEMM: h[n][o] = sum_k x[n][k] * W[o][k] ----------------
__global__ __launch_bounds__(256, 2)
void gemm_h_kernel(const float* __restrict__ x, const float* __restrict__ Wm) {
    constexpr int BM = 128, BN = 64, BK = 16;
    __shared__ float As[BK][BM + 4];
    __shared__ float Bs[BK][BN + 4];

    const int tid = threadIdx.x;
    const int m0 = blockIdx.y * BM;
    const int n0 = blockIdx.x * BN;
    const int ty = tid >> 4;          // 0..15 -> 8 rows each
    const int tx = tid & 15;          // 0..15 -> 4 cols each
    const int aRow = tid >> 2;        // 0..63
    const int aC   = (tid & 3) * 4;   // 0,4,8,12

    float acc[8][4] = {};

    for (int k0 = 0; k0 < KIN; k0 += BK) {
        float4 va0 = *(const float4*)(x  + (size_t)(m0 + aRow)      * KIN + k0 + aC);
        float4 va1 = *(const float4*)(x  + (size_t)(m0 + aRow + 64) * KIN + k0 + aC);
        float4 vb  = *(const float4*)(Wm + (size_t)(n0 + aRow)      * KIN + k0 + aC);

        As[aC + 0][aRow] = va0.x; As[aC + 1][aRow] = va0.y;
        As[aC + 2][aRow] = va0.z; As[aC + 3][aRow] = va0.w;
        As[aC + 0][aRow + 64] = va1.x; As[aC + 1][aRow + 64] = va1.y;
        As[aC + 2][aRow + 64] = va1.z; As[aC + 3][aRow + 64] = va1.w;
        Bs[aC + 0][aRow] = vb.x; Bs[aC + 1][aRow] = vb.y;
        Bs[aC + 2][aRow] = vb.z; Bs[aC + 3][aRow] = vb.w;
        __syncthreads();

        #pragma unroll
        for (int k = 0; k < BK; ++k) {
            float4 a0 = *(const float4*)&As[k][ty * 8];
            float4 a1 = *(const float4*)&As[k][ty * 8 + 4];
            float4 b  = *(const float4*)&Bs[k][tx * 4];
            float ar[8] = {a0.x, a0.y, a0.z, a0.w, a1.x, a1.y, a1.z, a1.w};
            float br[4] = {b.x, b.y, b.z, b.w};
            #pragma unroll
            for (int u = 0; u < 8; ++u)
                #pragma unroll
                for (int v = 0; v < 4; ++v)
                    acc[u][v] += ar[u] * br[v];
        }
        __syncthreads();
    }

    #pragma unroll
    for (int u = 0; u < 8; ++u) {
        int row = m0 + ty * 8 + u;
        float4 o = make_float4(acc[u][0], acc[u][1], acc[u][2], acc[u][3]);
        *(float4*)&g_h[(size_t)row * OUTD + n0 + tx * 4] = o;
    }
}

// ---------------- s1, s2 (+ sort key/idx init) ----------------
__global__ void s12_kernel(const float* __restrict__ a1, const float* __restrict__ a2) {
    int i = blockIdx.x;
    int k = threadIdx.x;  // 256
    float h = g_h[(size_t)i * OUTD + k];
    float v1 = h * a1[k];
    float v2 = h * a2[k];
    #pragma unroll
    for (int o = 16; o; o >>= 1) {
        v1 += __shfl_down_sync(0xFFFFFFFFu, v1, o);
        v2 += __shfl_down_sync(0xFFFFFFFFu, v2, o);
    }
    __shared__ float r1[8], r2[8];
    if ((k & 31) == 0) { r1[k >> 5] = v1; r2[k >> 5] = v2; }
    __syncthreads();
    if (k < 8) {
        v1 = r1[k]; v2 = r2[k];
        #pragma unroll
        for (int o = 4; o; o >>= 1) {
            v1 += __shfl_down_sync(0xFFu, v1, o);
            v2 += __shfl_down_sync(0xFFu, v2, o);
        }
        if (k == 0) { g_key[i] = v1; g_s2[i] = v2; g_idx[i] = i; }
    }
}

// ---------------- single-block bitonic sort of (s1, idx) ----------------
__global__ void sort_kernel() {
    extern __shared__ float smem[];
    float* sk = smem;                 // N floats
    int*   si = (int*)(smem + N);     // N ints
    int tid = threadIdx.x;
    for (int e = tid; e < N; e += 1024) { sk[e] = g_key[e]; si[e] = e; }
    __syncthreads();
    for (int size = 2; size <= N; size <<= 1) {
        for (int stride = size >> 1; stride > 0; stride >>= 1) {
            #pragma unroll 1
            for (int v = 0; v < N; v += 1024) {
                int e = v + tid;
                int p = e ^ stride;
                if (p > e) {
                    bool up = ((e & size) == 0);
                    float ke = sk[e], kp = sk[p];
                    if ((ke > kp) == up) {
                        sk[e] = kp; sk[p] = ke;
                        int t = si[e]; si[e] = si[p]; si[p] = t;
                    }
                }
            }
            __syncthreads();
        }
    }
    for (int e = tid; e < N; e += 1024) { g_key[e] = sk[e]; g_idx[e] = si[e]; }
}

// ---------------- pass 1: per-chunk weighted sums ----------------
__global__ void chunksum_kernel() {
    int c = blockIdx.x;
    int k = threadIdx.x;
    if (k >= W257) return;
    float m1 = g_key[N - 1];
    float acc1 = 0.f, acc2 = 0.f;
    for (int r = 0; r < CHL; ++r) {
        int p = c * CHL + r;
        float key = g_key[p];
        float w1 = __expf(0.f) , d = key - m1;  // placeholder to keep fast path
        w1 = expf(d);
        float w2 = expf(LRELU_ALPHA * d);
        float v = (k < OUTD) ? g_h[(size_t)g_idx[p] * OUTD + k] : 1.0f;
        acc1 += w1 * v;
        acc2 += w2 * v;
    }
    g_cs1[c * W257 + k] = acc1;
    g_cs2[c * W257 + k] = acc2;
}

// ---------------- pass 2: chunk-offset scans (1 block) ----------------
__global__ void chunkscan_kernel() {
    int k = threadIdx.x;
    if (k >= W257) return;
    float off = 0.f;
    for (int c = 0; c < NCH; ++c) {           // forward exclusive (alpha branch)
        g_co2[c * W257 + k] = off;
        off += g_cs2[c * W257 + k];
    }
    off = 0.f;
    for (int c = NCH - 1; c >= 0; --c) {      // backward exclusive (exp branch)
        g_co1[c * W257 + k] = off;
        off += g_cs1[c * W257 + k];
    }
}

// ---------------- pass 3: write full prefix/suffix arrays ----------------
__global__ void writescan_kernel() {
    int c = blockIdx.x;
    int k = threadIdx.x;
    if (k >= W257) return;
    float m1 = g_key[N - 1];

    // forward: P2[p] = sum_{q<p} exp(a*(s1_q-m1)) * v_q   (exclusive)
    float acc = g_co2[c * W257 + k];
    for (int r = 0; r < CHL; ++r) {
        int p = c * CHL + r;
        g_P2[(size_t)p * W257 + k] = acc;
        float v = (k < OUTD) ? g_h[(size_t)g_idx[p] * OUTD + k] : 1.0f;
        acc += expf(LRELU_ALPHA * (g_key[p] - m1)) * v;
    }
    if (c == NCH - 1) g_P2[(size_t)N * W257 + k] = acc;

    // backward: SE[p] = sum_{q>=p} exp(s1_q-m1) * v_q   (inclusive from p)
    acc = g_co1[c * W257 + k];
    for (int r = CHL - 1; r >= 0; --r) {
        int p = c * CHL + r;
        float v = (k < OUTD) ? g_h[(size_t)g_idx[p] * OUTD + k] : 1.0f;
        acc += expf(g_key[p] - m1) * v;
        g_SE[(size_t)p * W257 + k] = acc;
    }
    if (c == NCH - 1) g_SE[(size_t)N * W257 + k] = 0.f;
}

// ---------------- epilogue: per-row binary search + ratio ----------------
__global__ void out_kernel(float* __restrict__ out) {
    int i = blockIdx.x;
    int k = threadIdx.x;   // 256
    __shared__ int   sp;
    __shared__ float sr;
    if (k == 0) {
        float m1 = g_key[N - 1];
        float s2 = g_s2[i];
        float t = -s2;
        int lo = 0, hi = N;                  // first p with key[p] > t
        while (lo < hi) {
            int mid = (lo + hi) >> 1;
            if (g_key[mid] > t) hi = mid; else lo = mid + 1;
        }
        sp = lo;
        sr = expf((LRELU_ALPHA - 1.0f) * (s2 + m1));
    }
    __syncthreads();
    int p = sp;
    float r = sr;
    size_t base = (size_t)p * W257;
    float den = g_SE[base + OUTD] + r * g_P2[base + OUTD];
    float num = g_SE[base + k]    + r * g_P2[base + k];
    out[(size_t)i * OUTD + k] = num / den;
}

// ---------------- launch ----------------
extern "C" void kernel_launch(void* const* d_in, const int* in_sizes, int n_in,
                              void* d_out, int out_size) {
    const float* x  = (const float*)d_in[0];
    // d_in[1] = adj, unused by the module
    const float* Wm = (const float*)d_in[2];
    const float* a1 = (const float*)d_in[3];
    const float* a2 = (const float*)d_in[4];
    float* out = (float*)d_out;

    gemm_h_kernel<<<dim3(OUTD / 64, N / 128), 256>>>(x, Wm);
    s12_kernel<<<N, 256>>>(a1, a2);

    cudaFuncSetAttribute(sort_kernel, cudaFuncAttributeMaxDynamicSharedMemorySize, 65536);
    sort_kernel<<<1, 1024, 65536>>>();

    chunksum_kernel<<<NCH, 288>>>();
    chunkscan_kernel<<<1, 288>>>();
    writescan_kernel<<<NCH, 288>>>();
    out_kernel<<<N, 256>>>(out);
}

// round 3
// speedup vs baseline: 1.2314x; 1.2314x over previous
#include <cuda_runtime.h>
#include <cuda_bf16.h>
#include <cstdint>

#define LRELU_ALPHA 0.2f

constexpr int N    = 8192;
constexpr int KIN  = 512;
constexpr int OUTD = 256;
constexpr int W257 = OUTD + 1;
constexpr int NCH  = 256;
constexpr int CHL  = N / NCH;

// ---------------- scratch (device globals; no allocation) ----------------
__device__ float g_h[N * OUTD];
__device__ float g_s2[N];
__device__ float g_key[N];
__device__ int   g_idx[N];
__device__ float g_cs1[NCH * W257];
__device__ float g_cs2[NCH * W257];
__device__ float g_co1[NCH * W257];
__device__ float g_co2[NCH * W257];
__device__ float g_SE[(N + 1) * W257];
__device__ float g_P2[(N + 1) * W257];

__device__ __nv_bfloat16 g_xh[N * KIN];
__device__ __nv_bfloat16 g_xl[N * KIN];
__device__ __nv_bfloat16 g_wh[OUTD * KIN];
__device__ __nv_bfloat16 g_wl[OUTD * KIN];

__device__ __forceinline__ uint32_t smem_u32(const void* p) {
    uint32_t a;
    asm("{ .reg .u64 t; cvta.to.shared.u64 t, %1; cvt.u32.u64 %0, t; }" : "=r"(a) : "l"(p));
    return a;
}

// ==================== convert fp32 -> bf16 hi/lo ====================
__global__ void convert_kernel(const float* __restrict__ x, const float* __restrict__ Wm) {
    int i = blockIdx.x * blockDim.x + threadIdx.x;   // pair index
    constexpr int XT = N * KIN / 2;
    constexpr int WT = OUTD * KIN / 2;
    if (i < XT) {
        float2 v = ((const float2*)x)[i];
        __nv_bfloat16 h0 = __float2bfloat16(v.x), h1 = __float2bfloat16(v.y);
        __nv_bfloat16 l0 = __float2bfloat16(v.x - __bfloat162float(h0));
        __nv_bfloat16 l1 = __float2bfloat16(v.y - __bfloat162float(h1));
        ((__nv_bfloat162*)g_xh)[i] = __nv_bfloat162(h0, h1);
        ((__nv_bfloat162*)g_xl)[i] = __nv_bfloat162(l0, l1);
    } else if (i < XT + WT) {
        int j = i - XT;
        float2 v = ((const float2*)Wm)[j];
        __nv_bfloat16 h0 = __float2bfloat16(v.x), h1 = __float2bfloat16(v.y);
        __nv_bfloat16 l0 = __float2bfloat16(v.x - __bfloat162float(h0));
        __nv_bfloat16 l1 = __float2bfloat16(v.y - __bfloat162float(h1));
        ((__nv_bfloat162*)g_wh)[j] = __nv_bfloat162(h0, h1);
        ((__nv_bfloat162*)g_wl)[j] = __nv_bfloat162(l0, l1);
    }
}

// ==================== bf16 mma.sync GEMM: h = x @ W^T ====================
// CTA tile 128x128, 8 warps (2 along M x 4 along N), warp tile 64x32.
// K processed in 32-wide chunks from smem (padded stride 40 bf16 rows).
constexpr int SSTR = 40;   // smem row stride in bf16 elems

__device__ __forceinline__ void ldsm_x4(uint32_t (&r)[4], uint32_t addr) {
    asm volatile("ldmatrix.sync.aligned.m8n8.x4.shared.b16 {%0,%1,%2,%3}, [%4];"
                 : "=r"(r[0]), "=r"(r[1]), "=r"(r[2]), "=r"(r[3]) : "r"(addr));
}
__device__ __forceinline__ void mma_bf16(float (&c)[4], const uint32_t (&a)[4],
                                         uint32_t b0, uint32_t b1) {
    asm volatile(
        "mma.sync.aligned.m16n8k16.row.col.f32.bf16.bf16.f32 "
        "{%0,%1,%2,%3}, {%4,%5,%6,%7}, {%8,%9}, {%0,%1,%2,%3};"
        : "+f"(c[0]), "+f"(c[1]), "+f"(c[2]), "+f"(c[3])
        : "r"(a[0]), "r"(a[1]), "r"(a[2]), "r"(a[3]), "r"(b0), "r"(b1));
}

__global__ void __launch_bounds__(256, 1) gemm_tc_kernel() {
    __shared__ __nv_bfloat16 sAh[128 * SSTR];
    __shared__ __nv_bfloat16 sAl[128 * SSTR];
    __shared__ __nv_bfloat16 sBh[128 * SSTR];
    __shared__ __nv_bfloat16 sBl[128 * SSTR];

    const int tid  = threadIdx.x;
    const int wid  = tid >> 5;
    const int lane = tid & 31;
    const int wm   = wid & 1;        // 0..1 (64 rows each)
    const int wn   = wid >> 1;       // 0..3 (32 cols each)
    const int m0   = blockIdx.y * 128;
    const int n0   = blockIdx.x * 128;

    const uint32_t bAh = smem_u32(sAh);
    const uint32_t bAl = smem_u32(sAl);
    const uint32_t bBh = smem_u32(sBh);
    const uint32_t bBl = smem_u32(sBl);

    float acc[4][4][4] = {};

    for (int kc = 0; kc < KIN / 32; ++kc) {
        // cooperative load: 4 matrices, 128 rows x 32 cols each, uint4 (8 bf16)
        #pragma unroll
        for (int i = 0; i < 2; ++i) {
            int lin = i * 256 + tid;       // 0..511
            int r = lin >> 2, c4 = lin & 3;
            size_t go = (size_t)r * KIN + kc * 32 + c4 * 8;
            int so = r * SSTR + c4 * 8;
            *(uint4*)(sAh + so) = *(const uint4*)(g_xh + (size_t)m0 * KIN + go);
            *(uint4*)(sAl + so) = *(const uint4*)(g_xl + (size_t)m0 * KIN + go);
            *(uint4*)(sBh + so) = *(const uint4*)(g_wh + (size_t)n0 * KIN + go);
            *(uint4*)(sBl + so) = *(const uint4*)(g_wl + (size_t)n0 * KIN + go);
        }
        __syncthreads();

        #pragma unroll
        for (int kk = 0; kk < 2; ++kk) {   // two k16 steps per chunk
            uint32_t ah[4][4], al[4][4], bh[2][4], bl[2][4];
            // A fragments: row = wm*64 + mt*16 + (lane&15), col = kk*16 + (lane>>4)*8
            #pragma unroll
            for (int mt = 0; mt < 4; ++mt) {
                uint32_t off = (uint32_t)((wm * 64 + mt * 16 + (lane & 15)) * SSTR
                                          + kk * 16 + (lane >> 4) * 8) * 2;
                ldsm_x4(ah[mt], bAh + off);
                ldsm_x4(al[mt], bAl + off);
            }
            // B fragments: per pair ntp covers 16 n-rows, both k-halves
            #pragma unroll
            for (int ntp = 0; ntp < 2; ++ntp) {
                uint32_t off = (uint32_t)((wn * 32 + ntp * 16 + ((lane >> 4) * 8) + (lane & 7)) * SSTR
                                          + kk * 16 + ((lane >> 3) & 1) * 8) * 2;
                ldsm_x4(bh[ntp], bBh + off);
                ldsm_x4(bl[ntp], bBl + off);
            }
            #pragma unroll
            for (int mt = 0; mt < 4; ++mt)
                #pragma unroll
                for (int nf = 0; nf < 4; ++nf) {
                    uint32_t bh0 = bh[nf >> 1][(nf & 1) * 2], bh1 = bh[nf >> 1][(nf & 1) * 2 + 1];
                    uint32_t bl0 = bl[nf >> 1][(nf & 1) * 2], bl1 = bl[nf >> 1][(nf & 1) * 2 + 1];
                    mma_bf16(acc[mt][nf], ah[mt], bh0, bh1);   // hi*hi
                    mma_bf16(acc[mt][nf], ah[mt], bl0, bl1);   // hi*lo
                    mma_bf16(acc[mt][nf], al[mt], bh0, bh1);   // lo*hi
                }
        }
        __syncthreads();
    }

    // epilogue: c layout -> g_h (float2 stores)
    #pragma unroll
    for (int mt = 0; mt < 4; ++mt)
        #pragma unroll
        for (int nf = 0; nf < 4; ++nf) {
            int row0 = m0 + wm * 64 + mt * 16 + (lane >> 2);
            int col  = n0 + wn * 32 + nf * 8 + (lane & 3) * 2;
            *(float2*)&g_h[(size_t)row0 * OUTD + col] =
                make_float2(acc[mt][nf][0], acc[mt][nf][1]);
            *(float2*)&g_h[(size_t)(row0 + 8) * OUTD + col] =
                make_float2(acc[mt][nf][2], acc[mt][nf][3]);
        }
}

// ==================== s1, s2 ====================
__global__ void s12_kernel(const float* __restrict__ a1, const float* __restrict__ a2) {
    int i = blockIdx.x;
    int k = threadIdx.x;
    float h = g_h[(size_t)i * OUTD + k];
    float v1 = h * a1[k];
    float v2 = h * a2[k];
    #pragma unroll
    for (int o = 16; o; o >>= 1) {
        v1 += __shfl_down_sync(0xFFFFFFFFu, v1, o);
        v2 += __shfl_down_sync(0xFFFFFFFFu, v2, o);
    }
    __shared__ float r1[8], r2[8];
    if ((k & 31) == 0) { r1[k >> 5] = v1; r2[k >> 5] = v2; }
    __syncthreads();
    if (k < 8) {
        v1 = r1[k]; v2 = r2[k];
        #pragma unroll
        for (int o = 4; o; o >>= 1) {
            v1 += __shfl_down_sync(0xFFu, v1, o);
            v2 += __shfl_down_sync(0xFFu, v2, o);
        }
        if (k == 0) { g_key[i] = v1; g_s2[i] = v2; }
    }
}

// ==================== packed-uint64 bitonic sort, register-fused ====================
#define CE(i, j, up) { if ((v[i] > v[j]) == (up)) { unsigned long long t = v[i]; v[i] = v[j]; v[j] = t; } }

__global__ void sort_kernel() {
    extern __shared__ unsigned long long s[];   // 8192 * 8B = 64KB
    const int tid = threadIdx.x;
    const int base = tid * 8;

    for (int e = tid; e < N; e += 1024) {
        uint32_t u = __float_as_uint(g_key[e]);
        u ^= (u & 0x80000000u) ? 0xFFFFFFFFu : 0x80000000u;
        s[e] = ((unsigned long long)u << 13) | (unsigned)e;
    }
    __syncthreads();

    unsigned long long v[8];
    #pragma unroll
    for (int i = 0; i < 8; ++i) v[i] = s[base + i];
    CE(0,1,true) CE(2,3,false) CE(4,5,true) CE(6,7,false)
    CE(0,2,true) CE(1,3,true)  CE(4,6,false) CE(5,7,false)
    CE(0,1,true) CE(2,3,true)  CE(4,5,false) CE(6,7,false)
    {
        bool up8 = ((tid & 1) == 0);
        CE(0,4,up8) CE(1,5,up8) CE(2,6,up8) CE(3,7,up8)
        CE(0,2,up8) CE(1,3,up8) CE(4,6,up8) CE(5,7,up8)
        CE(0,1,up8) CE(2,3,up8) CE(4,5,up8) CE(6,7,up8)
    }
    #pragma unroll
    for (int i = 0; i < 8; ++i) s[base + i] = v[i];
    __syncthreads();

    for (int size = 16; size <= N; size <<= 1) {
        for (int stride = size >> 1; stride >= 8; stride >>= 1) {
            #pragma unroll 1
            for (int i = tid; i < N / 2; i += 1024) {
                int a = ((i & ~(stride - 1)) << 1) | (i & (stride - 1));
                int b = a + stride;
                bool up = ((a & size) == 0);
                unsigned long long x = s[a], y = s[b];
                if ((x > y) == up) { s[a] = y; s[b] = x; }
            }
            __syncthreads();
        }
        #pragma unroll
        for (int i = 0; i < 8; ++i) v[i] = s[base + i];
        bool up = ((base & size) == 0);
        CE(0,4,up) CE(1,5,up) CE(2,6,up) CE(3,7,up)
        CE(0,2,up) CE(1,3,up) CE(4,6,up) CE(5,7,up)
        CE(0,1,up) CE(2,3,up) CE(4,5,up) CE(6,7,up)
        #pragma unroll
        for (int i = 0; i < 8; ++i) s[base + i] = v[i];
        __syncthreads();
    }

    for (int e = tid; e < N; e += 1024) {
        unsigned long long p = s[e];
        int idx = (int)(p & 0x1FFFu);
        uint32_t u = (uint32_t)(p >> 13);
        u ^= (u & 0x80000000u) ? 0x80000000u : 0xFFFFFFFFu;
        g_key[e] = __uint_as_float(u);
        g_idx[e] = idx;
    }
}

// ==================== pass 1: per-chunk weighted sums ====================
__global__ void chunksum_kernel() {
    int c = blockIdx.x;
    int k = threadIdx.x;
    if (k >= W257) return;
    float m1 = g_key[N - 1];
    float acc1 = 0.f, acc2 = 0.f;
    #pragma unroll 4
    for (int r = 0; r < CHL; ++r) {
        int p = c * CHL + r;
        float d = g_key[p] - m1;
        float w1 = __expf(d);
        float w2 = __expf(LRELU_ALPHA * d);
        float v = (k < OUTD) ? g_h[(size_t)g_idx[p] * OUTD + k] : 1.0f;
        acc1 += w1 * v;
        acc2 += w2 * v;
    }
    g_cs1[c * W257 + k] = acc1;
    g_cs2[c * W257 + k] = acc2;
}

// ==================== pass 2: chunk-offset scans ====================
__global__ void chunkscan_kernel() {
    int k = threadIdx.x;
    if (k >= W257) return;
    float off = 0.f;
    #pragma unroll 4
    for (int c = 0; c < NCH; ++c) {
        g_co2[c * W257 + k] = off;
        off += g_cs2[c * W257 + k];
    }
    off = 0.f;
    #pragma unroll 4
    for (int c = NCH - 1; c >= 0; --c) {
        g_co1[c * W257 + k] = off;
        off += g_cs1[c * W257 + k];
    }
}

// ==================== pass 3: full prefix/suffix arrays ====================
__global__ void writescan_kernel() {
    int c = blockIdx.x;
    int k = threadIdx.x;
    if (k >= W257) return;
    float m1 = g_key[N - 1];

    float acc = g_co2[c * W257 + k];
    for (int r = 0; r < CHL; ++r) {
        int p = c * CHL + r;
        g_P2[(size_t)p * W257 + k] = acc;
        float v = (k < OUTD) ? g_h[(size_t)g_idx[p] * OUTD + k] : 1.0f;
        acc += __expf(LRELU_ALPHA * (g_key[p] - m1)) * v;
    }
    if (c == NCH - 1) g_P2[(size_t)N * W257 + k] = acc;

    acc = g_co1[c * W257 + k];
    for (int r = CHL - 1; r >= 0; --r) {
        int p = c * CHL + r;
        float v = (k < OUTD) ? g_h[(size_t)g_idx[p] * OUTD + k] : 1.0f;
        acc += __expf(g_key[p] - m1) * v;
        g_SE[(size_t)p * W257 + k] = acc;
    }
    if (c == NCH - 1) g_SE[(size_t)N * W257 + k] = 0.f;
}

// ==================== epilogue ====================
__global__ void out_kernel(float* __restrict__ out) {
    int i = blockIdx.x;
    int k = threadIdx.x;
    __shared__ int   sp;
    __shared__ float sr;
    if (k == 0) {
        float m1 = g_key[N - 1];
        float s2 = g_s2[i];
        float t = -s2;
        int lo = 0, hi = N;
        while (lo < hi) {
            int mid = (lo + hi) >> 1;
            if (g_key[mid] > t) hi = mid; else lo = mid + 1;
        }
        sp = lo;
        sr = __expf((LRELU_ALPHA - 1.0f) * (s2 + m1));
    }
    __syncthreads();
    size_t basep = (size_t)sp * W257;
    float r = sr;
    float den = g_SE[basep + OUTD] + r * g_P2[basep + OUTD];
    float num = g_SE[basep + k]    + r * g_P2[basep + k];
    out[(size_t)i * OUTD + k] = num / den;
}

// ==================== launch ====================
extern "C" void kernel_launch(void* const* d_in, const int* in_sizes, int n_in,
                              void* d_out, int out_size) {
    const float* x  = (const float*)d_in[0];
    const float* Wm = (const float*)d_in[2];
    const float* a1 = (const float*)d_in[3];
    const float* a2 = (const float*)d_in[4];
    float* out = (float*)d_out;

    int pairs = (N * KIN + OUTD * KIN) / 2;
    convert_kernel<<<(pairs + 255) / 256, 256>>>(x, Wm);

    gemm_tc_kernel<<<dim3(OUTD / 128, N / 128), 256>>>();

    s12_kernel<<<N, 256>>>(a1, a2);

    cudaFuncSetAttribute(sort_kernel, cudaFuncAttributeMaxDynamicSharedMemorySize, 65536);
    sort_kernel<<<1, 1024, 65536>>>();

    chunksum_kernel<<<NCH, 288>>>();
    chunkscan_kernel<<<1, 288>>>();
    writescan_kernel<<<NCH, 288>>>();
    out_kernel<<<N, 256>>>(out);
}